// round 12
// baseline (speedup 1.0000x reference)
#include <cuda_runtime.h>
#include <cstdint>
#include <math.h>

#define BATCH 16
#define NN 1024
#define DD 256
#define HH 128

__device__ float g_gate[BATCH * NN];
__device__ float g_axin[BATCH * NN * DD];
__device__ float g_axout[BATCH * NN * DD];
__device__ float g_xbuf[BATCH * NN * DD];
// pair-packed operands: float2 = (v[k], v[k+4]) for k = 8*K8 + c, c in 0..3
__device__ float2 g_Ainp[BATCH * NN * NN / 2];   // [b][m][K8][c]
__device__ float2 g_Aoutp[BATCH * NN * NN / 2];  // [b][m][K8][c]
__device__ float2 g_xp[BATCH * (NN / 8) * 4 * DD];  // [b][K8][c][n]

__device__ __forceinline__ float tf32f(float x) {
    uint32_t u;
    asm("cvt.rna.tf32.f32 %0, %1;" : "=r"(u) : "f"(x));
    return __uint_as_float(u);
}
__device__ __forceinline__ uint32_t smem_u32(const void* p) {
    uint32_t a;
    asm("{ .reg .u64 t; cvta.to.shared.u64 t, %1; cvt.u32.u64 %0, t; }" : "=r"(a) : "l"(p));
    return a;
}
__device__ __forceinline__ void mma8(float* c, const uint32_t* a, const uint32_t* b) {
    asm volatile(
        "mma.sync.aligned.m16n8k8.row.col.f32.tf32.tf32.f32 "
        "{%0,%1,%2,%3}, {%4,%5,%6,%7}, {%8,%9}, {%0,%1,%2,%3};"
        : "+f"(c[0]), "+f"(c[1]), "+f"(c[2]), "+f"(c[3])
        : "r"(a[0]), "r"(a[1]), "r"(a[2]), "r"(a[3]), "r"(b[0]), "r"(b[1]));
}
#define CP16(dst, src) \
    asm volatile("cp.async.cg.shared.global [%0], [%1], 16;" :: "r"(dst), "l"(src))
#define CPCOMMIT() asm volatile("cp.async.commit_group;" ::: "memory")
#define CPWAIT1() asm volatile("cp.async.wait_group 1;" ::: "memory")

// ---------------------------------------------------------------------------
// gate g = sigmoid(x @ rg)
// ---------------------------------------------------------------------------
__global__ void gate_kernel(const float* __restrict__ x, const float* __restrict__ rg) {
    int row = blockIdx.x * 8 + threadIdx.y;
    int lane = threadIdx.x;
    const float* xr = x + (size_t)row * DD;
    float s = 0.f;
#pragma unroll
    for (int i = 0; i < 8; i++) s += xr[lane + i * 32] * rg[lane + i * 32];
#pragma unroll
    for (int o = 16; o; o >>= 1) s += __shfl_xor_sync(0xffffffffu, s, o);
    if (lane == 0) g_gate[row] = 1.f / (1.f + expf(-s));
}

// ---------------------------------------------------------------------------
// xpack: g_xp[b][K8][c][n] = (tf32(x[8K8+c][n]), tf32(x[8K8+c+4][n]))
// ---------------------------------------------------------------------------
__global__ void xpack_k(const float* __restrict__ x) {
    const int K8 = blockIdx.x;      // 0..127
    const int b = blockIdx.y;
    const int n = threadIdx.x;      // 0..255
    const float* xb = x + (size_t)b * NN * DD;
    float2* outb = g_xp + (size_t)b * 128 * 4 * DD;
#pragma unroll
    for (int c = 0; c < 4; c++) {
        float v0 = tf32f(xb[(size_t)(8 * K8 + c) * DD + n]);
        float v1 = tf32f(xb[(size_t)(8 * K8 + c + 4) * DD + n]);
        outb[(size_t)(K8 * 4 + c) * DD + n] = make_float2(v0, v1);
    }
}

// ---------------------------------------------------------------------------
// blend: A_in[m][k] = rnd(g[m]*dep[m][k] + (1-g[m])*lat[m][k])    (pack)
//        A_out[m][k] = rnd(g[m]*dep[k][m] + (1-g[m])*lat[k][m])   (pack)
// packed float index: m*1024 + (k>>3)*8 + (k&3)*2 + ((k>>2)&1)
// ---------------------------------------------------------------------------
__global__ __launch_bounds__(256) void blend_k(const float* __restrict__ dep,
                                               const float* __restrict__ lat) {
    __shared__ float sd[64][65];
    __shared__ float sl[64][65];
    __shared__ float sgr[64], sgc[64];
    const int b = blockIdx.z;
    const int r0 = blockIdx.y * 64, c0 = blockIdx.x * 64;
    const int tid = threadIdx.x;

    if (tid < 64) sgr[tid] = g_gate[b * NN + r0 + tid];
    else if (tid < 128) sgc[tid - 64] = g_gate[b * NN + c0 + tid - 64];
    __syncthreads();

    const size_t base = (size_t)b * NN * NN;
    float* Ain = (float*)g_Ainp + base;
    float* Aout = (float*)g_Aoutp + base;
#pragma unroll
    for (int it = 0; it < 16; it++) {
        int idx = tid + it * 256;
        int row = idx >> 6, col = idx & 63;
        size_t off = base + (size_t)(r0 + row) * NN + c0 + col;
        float d = dep[off], l = lat[off];
        sd[row][col] = d;
        sl[row][col] = l;
        float g = sgr[row];
        int m = r0 + row, k = c0 + col;
        Ain[(size_t)m * 1024 + (k >> 3) * 8 + (k & 3) * 2 + ((k >> 2) & 1)] =
            tf32f(g * d + (1.f - g) * l);
    }
    __syncthreads();
#pragma unroll
    for (int it = 0; it < 16; it++) {
        int idx = tid + it * 256;
        int jj = idx >> 6, ii = idx & 63;
        float g = sgc[jj];
        float v = tf32f(g * sd[ii][jj] + (1.f - g) * sl[ii][jj]);
        int m = c0 + jj, k = r0 + ii;
        Aout[(size_t)m * 1024 + (k >> 3) * 8 + (k & 3) * 2 + ((k >> 2) & 1)] = v;
    }
}

// ---------------------------------------------------------------------------
// Unified GEMM on packed operands. BM=64, BN=256, BK=32.
// 8 warps (2m x 4n), warp tile 32x64. 2-stage cp.async, 2 CTAs/SM.
// All fragment loads are single LDS.64, conflict-free.
// smem stage: A 64 rows x 40 words (10240 B) + X 16 rows x 260 float2 (33280 B)
// ---------------------------------------------------------------------------
#define G_STAGE 43520
#define G_SMEM (2 * G_STAGE)

__global__ __launch_bounds__(256, 2) void ax_gemm(int dummy) {
    extern __shared__ char smem[];
    const uint32_t sb = smem_u32(smem);
    const int tid = threadIdx.x, lane = tid & 31, wid = tid >> 5;
    const int id = blockIdx.x;
    const int side = id & 1;
    const int m0 = (id >> 1) * 64;
    const int b = blockIdx.y;
    const int cc = lane & 3, gg = lane >> 2;

    const char* Ab = (const char*)((side ? g_Aoutp : g_Ainp) +
                                   (size_t)b * (NN * NN / 2) + (size_t)m0 * 512);
    const char* Xb = (const char*)(g_xp + (size_t)b * 128 * 4 * DD);
    float* outb = (side ? g_axout : g_axin) + (size_t)b * NN * DD + (size_t)m0 * DD;

    auto issue = [&](int it) {
        const uint32_t so = sb + (it & 1) * G_STAGE;
        // A: 64 rows x 128 B contiguous (K8 = it*4 .. it*4+3)
#pragma unroll
        for (int i = 0; i < 2; i++) {
            int idx = tid + i * 256;
            int r = idx >> 3, ch = idx & 7;
            CP16(so + r * 160 + ch * 16, Ab + (size_t)r * 4096 + it * 128 + ch * 16);
        }
        // X: 16 rows ((K8,c)) x 2048 B each
#pragma unroll
        for (int i = 0; i < 8; i++) {
            int idx = tid + i * 256;
            int row = idx >> 7, ch = idx & 127;
            CP16(so + 10240 + row * 2080 + ch * 16,
                 Xb + (size_t)(it * 16 + row) * 2048 + ch * 16);
        }
        CPCOMMIT();
    };

    issue(0);

    float acc[2][8][4] = {};
    const int wm = wid & 1, wn = wid >> 1;

    for (int it = 0; it < 32; it++) {
        if (it + 1 < 32) issue(it + 1); else CPCOMMIT();
        CPWAIT1();
        __syncthreads();
        const char* st = smem + (it & 1) * G_STAGE;
        const float2* sA = (const float2*)st;          // row stride 20 float2
        const float2* sX = (const float2*)(st + 10240);  // row stride 260 float2
#pragma unroll
        for (int k8 = 0; k8 < 4; k8++) {
            uint32_t a[2][4], bx[8][2];
#pragma unroll
            for (int mt = 0; mt < 2; mt++) {
                int r = wm * 32 + mt * 16 + gg;
                float2 u = sA[r * 20 + k8 * 4 + cc];
                float2 v = sA[(r + 8) * 20 + k8 * 4 + cc];
                a[mt][0] = __float_as_uint(u.x);
                a[mt][1] = __float_as_uint(v.x);
                a[mt][2] = __float_as_uint(u.y);
                a[mt][3] = __float_as_uint(v.y);
            }
#pragma unroll
            for (int nt = 0; nt < 8; nt++) {
                int n = wn * 64 + nt * 8 + gg;
                float2 w = sX[(k8 * 4 + cc) * 260 + n];
                bx[nt][0] = __float_as_uint(w.x);
                bx[nt][1] = __float_as_uint(w.y);
            }
#pragma unroll
            for (int mt = 0; mt < 2; mt++)
#pragma unroll
                for (int nt = 0; nt < 8; nt++) mma8(acc[mt][nt], a[mt], bx[nt]);
        }
        __syncthreads();
    }

#pragma unroll
    for (int mt = 0; mt < 2; mt++) {
        int r0 = wm * 32 + mt * 16 + gg;
        float* o0 = outb + (size_t)r0 * DD;
        float* o1 = o0 + 8 * DD;
#pragma unroll
        for (int nt = 0; nt < 8; nt++) {
            int c = wn * 64 + nt * 8 + cc * 2;
            *(float2*)(o0 + c) = make_float2(acc[mt][nt][0], acc[mt][nt][1]);
            *(float2*)(o1 + c) = make_float2(acc[mt][nt][2], acc[mt][nt][3]);
        }
    }
}

// ---------------------------------------------------------------------------
// hfuse: gcn gates + residual (fp32 x), then dual fc (tf32), LN, exact GELU
// ---------------------------------------------------------------------------
#define HF_SUF 67584                 // 2*32*264*4
#define HF_SMEM (HF_SUF + 40960)     // + 2*128*40*4

__global__ __launch_bounds__(256) void hfuse_kernel(
    const float* __restrict__ x,
    const float* __restrict__ Wi, const float* __restrict__ Wo,
    const float* __restrict__ bi, const float* __restrict__ bo,
    const float* __restrict__ wgi, const float* __restrict__ wgo,
    const float* __restrict__ bgi, const float* __restrict__ bgo,
    const float* __restrict__ lng, const float* __restrict__ lnb,
    float* __restrict__ out) {
    extern __shared__ char smem[];
    float* sUf = (float*)smem;            // [side][32][264]
    float* sW = (float*)(smem + HF_SUF);  // [side][128][40]

    const int row0 = blockIdx.x * 32;
    const int tid = threadIdx.x;
    const int lane = tid & 31;
    const int wid = tid >> 5;
    const int cc = lane & 3, gg = lane >> 2;

    const float bgi0 = bgi[0], bgo0 = bgo[0];
#pragma unroll
    for (int i = 0; i < 4; i++) {
        int r = wid * 4 + i;
        size_t base = (size_t)(row0 + r) * DD;
        float ui[8], uo[8], xv[8];
        float si = 0.f, so = 0.f;
#pragma unroll
        for (int jj = 0; jj < 8; jj++) {
            int d = lane + jj * 32;
            ui[jj] = g_axin[base + d];
            uo[jj] = g_axout[base + d];
            xv[jj] = x[base + d];
            si += ui[jj] * wgi[d];
            so += uo[jj] * wgo[d];
        }
#pragma unroll
        for (int o = 16; o; o >>= 1) {
            si += __shfl_xor_sync(0xffffffffu, si, o);
            so += __shfl_xor_sync(0xffffffffu, so, o);
        }
        si = 1.f / (1.f + expf(-si));
        so = 1.f / (1.f + expf(-so));
#pragma unroll
        for (int jj = 0; jj < 8; jj++) {
            int d = lane + jj * 32;
            sUf[r * 264 + d] = tf32f(ui[jj] * si + bgi0 + xv[jj]);
            sUf[32 * 264 + r * 264 + d] = tf32f(uo[jj] * so + bgo0 + xv[jj]);
        }
    }
    __syncthreads();

    const int side = wid >> 2;
    const int nb = (wid & 3) * 32;
    const float* su = sUf + side * 32 * 264;
    float* swb = sW + side * 128 * 40;

    float acc[2][4][4] = {};
    for (int k0 = 0; k0 < DD; k0 += 32) {
#pragma unroll
        for (int s = 0; s < 2; s++) {
            const float* Wsrc = s ? Wo : Wi;
            float* wdst = sW + s * 128 * 40;
#pragma unroll
            for (int i2 = 0; i2 < 4; i2++) {
                int idx = tid + i2 * 256;
                int h = idx >> 3, c4 = idx & 7;
                float4 v = *(const float4*)(Wsrc + (size_t)h * DD + k0 + c4 * 4);
                float4 w = make_float4(tf32f(v.x), tf32f(v.y), tf32f(v.z), tf32f(v.w));
                *(float4*)(wdst + h * 40 + c4 * 4) = w;
            }
        }
        __syncthreads();

#pragma unroll
        for (int j = 0; j < 4; j++) {
            const int kp = j * 8 + 2 * cc;
            uint32_t a[2][4], bb[4][2];
#pragma unroll
            for (int mt = 0; mt < 2; mt++) {
                int r = mt * 16 + gg;
                float2 v0 = *(const float2*)(su + r * 264 + k0 + kp);
                float2 v1 = *(const float2*)(su + (r + 8) * 264 + k0 + kp);
                a[mt][0] = __float_as_uint(v0.x);
                a[mt][1] = __float_as_uint(v1.x);
                a[mt][2] = __float_as_uint(v0.y);
                a[mt][3] = __float_as_uint(v1.y);
            }
#pragma unroll
            for (int nt = 0; nt < 4; nt++) {
                int n = nb + nt * 8 + gg;
                float2 v = *(const float2*)(swb + n * 40 + kp);
                bb[nt][0] = __float_as_uint(v.x);
                bb[nt][1] = __float_as_uint(v.y);
            }
#pragma unroll
            for (int mt = 0; mt < 2; mt++)
#pragma unroll
                for (int nt = 0; nt < 4; nt++) mma8(acc[mt][nt], a[mt], bb[nt]);
        }
        __syncthreads();
    }

    float* sHp = sW;  // [32][264]
    const float* bias = side ? bo : bi;
#pragma unroll
    for (int mt = 0; mt < 2; mt++) {
#pragma unroll
        for (int nt = 0; nt < 4; nt++) {
            int cl = nb + nt * 8 + cc * 2;
            float b0 = 2.f * bias[cl], b1 = 2.f * bias[cl + 1];
            int col = side * HH + cl;
            int r = mt * 16 + gg;
            sHp[r * 264 + col] = acc[mt][nt][0] + b0;
            sHp[r * 264 + col + 1] = acc[mt][nt][1] + b1;
            sHp[(r + 8) * 264 + col] = acc[mt][nt][2] + b0;
            sHp[(r + 8) * 264 + col + 1] = acc[mt][nt][3] + b1;
        }
    }
    __syncthreads();

#pragma unroll
    for (int i = 0; i < 4; i++) {
        int r = wid * 4 + i;
        float v[8];
        float s = 0.f, sq = 0.f;
#pragma unroll
        for (int jj = 0; jj < 8; jj++) {
            v[jj] = sHp[r * 264 + lane + jj * 32];
            s += v[jj];
            sq += v[jj] * v[jj];
        }
#pragma unroll
        for (int o = 16; o; o >>= 1) {
            s += __shfl_xor_sync(0xffffffffu, s, o);
            sq += __shfl_xor_sync(0xffffffffu, sq, o);
        }
        float mu = s * (1.f / 256.f);
        float var = sq * (1.f / 256.f) - mu * mu;
        float rs = rsqrtf(var + 1e-5f);
#pragma unroll
        for (int jj = 0; jj < 8; jj++) {
            int col = lane + jj * 32;
            float y = (v[jj] - mu) * rs * lng[col] + lnb[col];
            float ge = 0.5f * y * (1.f + erff(y * 0.70710678118654752f));
            out[(size_t)(row0 + r) * DD + col] = ge;
        }
    }
}

// ---------------------------------------------------------------------------
extern "C" void kernel_launch(void* const* d_in, const int* in_sizes, int n_in,
                              void* d_out, int out_size) {
    (void)in_sizes; (void)n_in; (void)out_size;
    const float* x0  = (const float*)d_in[0];
    const float* lat = (const float*)d_in[1];
    const float* dep = (const float*)d_in[2];
    const float* rg  = (const float*)d_in[3];
    const float* wgi = (const float*)d_in[4];
    const float* bgi = (const float*)d_in[5];
    const float* wgo = (const float*)d_in[6];
    const float* bgo = (const float*)d_in[7];
    const float* fiw = (const float*)d_in[8];
    const float* fib = (const float*)d_in[9];
    const float* fow = (const float*)d_in[10];
    const float* fob = (const float*)d_in[11];
    const float* lng = (const float*)d_in[12];
    const float* lnb = (const float*)d_in[13];
    float* out = (float*)d_out;

    float* xbuf_p = nullptr;
    cudaGetSymbolAddress((void**)&xbuf_p, g_xbuf);

    cudaFuncSetAttribute(ax_gemm, cudaFuncAttributeMaxDynamicSharedMemorySize, G_SMEM);
    cudaFuncSetAttribute(hfuse_kernel, cudaFuncAttributeMaxDynamicSharedMemorySize, HF_SMEM);

    for (int l = 0; l < 2; l++) {
        const float* x = (l == 0) ? x0 : (const float*)xbuf_p;
        float* xo = (l == 1) ? out : xbuf_p;
        gate_kernel<<<2048, dim3(32, 8)>>>(x, rg + l * DD);
        xpack_k<<<dim3(128, 16), 256>>>(x);
        blend_k<<<dim3(16, 16, 16), 256>>>(dep, lat);
        ax_gemm<<<dim3(32, 16), 256, G_SMEM>>>(0);
        hfuse_kernel<<<512, 256, HF_SMEM>>>(
            x,
            fiw + (size_t)l * HH * DD, fow + (size_t)l * HH * DD,
            fib + l * HH, fob + l * HH,
            wgi + l * DD, wgo + l * DD, bgi + l, bgo + l,
            lng + l * 2 * HH, lnb + l * 2 * HH, xo);
    }
}

// round 13
// speedup vs baseline: 1.0057x; 1.0057x over previous
#include <cuda_runtime.h>
#include <cstdint>
#include <math.h>

#define BATCH 16
#define NN 1024
#define DD 256
#define HH 128

__device__ float g_gate[BATCH * NN];
__device__ float g_axin[BATCH * NN * DD];
__device__ float g_axout[BATCH * NN * DD];
__device__ float g_xbuf[BATCH * NN * DD];
// pair-packed operands: float2 = (v[k], v[k+4]) for k = 8*K8 + c, c in 0..3
__device__ float2 g_Ainp[BATCH * NN * NN / 2];   // [b][m][K8][c]
__device__ float2 g_Aoutp[BATCH * NN * NN / 2];  // [b][m][K8][c]
__device__ float2 g_xp[BATCH * (NN / 8) * 4 * DD];  // [b][K8][c][n]

__device__ __forceinline__ float tf32f(float x) {
    uint32_t u;
    asm("cvt.rna.tf32.f32 %0, %1;" : "=r"(u) : "f"(x));
    return __uint_as_float(u);
}
__device__ __forceinline__ uint32_t smem_u32(const void* p) {
    uint32_t a;
    asm("{ .reg .u64 t; cvta.to.shared.u64 t, %1; cvt.u32.u64 %0, t; }" : "=r"(a) : "l"(p));
    return a;
}
__device__ __forceinline__ void mma8(float* c, const uint32_t* a, const uint32_t* b) {
    asm volatile(
        "mma.sync.aligned.m16n8k8.row.col.f32.tf32.tf32.f32 "
        "{%0,%1,%2,%3}, {%4,%5,%6,%7}, {%8,%9}, {%0,%1,%2,%3};"
        : "+f"(c[0]), "+f"(c[1]), "+f"(c[2]), "+f"(c[3])
        : "r"(a[0]), "r"(a[1]), "r"(a[2]), "r"(a[3]), "r"(b[0]), "r"(b[1]));
}
#define CP16(dst, src) \
    asm volatile("cp.async.cg.shared.global [%0], [%1], 16;" :: "r"(dst), "l"(src))
#define CPCOMMIT() asm volatile("cp.async.commit_group;" ::: "memory")
#define CPWAIT1() asm volatile("cp.async.wait_group 1;" ::: "memory")

// ---------------------------------------------------------------------------
// gate g = sigmoid(x @ rg)
// ---------------------------------------------------------------------------
__global__ void gate_kernel(const float* __restrict__ x, const float* __restrict__ rg) {
    int row = blockIdx.x * 8 + threadIdx.y;
    int lane = threadIdx.x;
    const float* xr = x + (size_t)row * DD;
    float s = 0.f;
#pragma unroll
    for (int i = 0; i < 8; i++) s += xr[lane + i * 32] * rg[lane + i * 32];
#pragma unroll
    for (int o = 16; o; o >>= 1) s += __shfl_xor_sync(0xffffffffu, s, o);
    if (lane == 0) g_gate[row] = 1.f / (1.f + expf(-s));
}

// ---------------------------------------------------------------------------
// xpack: g_xp[b][K8][c][n] = (tf32(x[8K8+c][n]), tf32(x[8K8+c+4][n]))
// ---------------------------------------------------------------------------
__global__ void xpack_k(const float* __restrict__ x) {
    const int K8 = blockIdx.x;      // 0..127
    const int b = blockIdx.y;
    const int n = threadIdx.x;      // 0..255
    const float* xb = x + (size_t)b * NN * DD;
    float2* outb = g_xp + (size_t)b * 128 * 4 * DD;
#pragma unroll
    for (int c = 0; c < 4; c++) {
        float v0 = tf32f(xb[(size_t)(8 * K8 + c) * DD + n]);
        float v1 = tf32f(xb[(size_t)(8 * K8 + c + 4) * DD + n]);
        outb[(size_t)(K8 * 4 + c) * DD + n] = make_float2(v0, v1);
    }
}

// ---------------------------------------------------------------------------
// blend: A_in[m][k] = rnd(g[m]*dep[m][k] + (1-g[m])*lat[m][k])    (pack)
//        A_out[m][k] = rnd(g[m]*dep[k][m] + (1-g[m])*lat[k][m])   (pack)
// packed float index: m*1024 + (k>>3)*8 + (k&3)*2 + ((k>>2)&1)
// ---------------------------------------------------------------------------
__global__ __launch_bounds__(256) void blend_k(const float* __restrict__ dep,
                                               const float* __restrict__ lat) {
    __shared__ float sd[64][65];
    __shared__ float sl[64][65];
    __shared__ float sgr[64], sgc[64];
    const int b = blockIdx.z;
    const int r0 = blockIdx.y * 64, c0 = blockIdx.x * 64;
    const int tid = threadIdx.x;

    if (tid < 64) sgr[tid] = g_gate[b * NN + r0 + tid];
    else if (tid < 128) sgc[tid - 64] = g_gate[b * NN + c0 + tid - 64];
    __syncthreads();

    const size_t base = (size_t)b * NN * NN;
    float* Ain = (float*)g_Ainp + base;
    float* Aout = (float*)g_Aoutp + base;
#pragma unroll
    for (int it = 0; it < 16; it++) {
        int idx = tid + it * 256;
        int row = idx >> 6, col = idx & 63;
        size_t off = base + (size_t)(r0 + row) * NN + c0 + col;
        float d = dep[off], l = lat[off];
        sd[row][col] = d;
        sl[row][col] = l;
        float g = sgr[row];
        int m = r0 + row, k = c0 + col;
        Ain[(size_t)m * 1024 + (k >> 3) * 8 + (k & 3) * 2 + ((k >> 2) & 1)] =
            tf32f(g * d + (1.f - g) * l);
    }
    __syncthreads();
#pragma unroll
    for (int it = 0; it < 16; it++) {
        int idx = tid + it * 256;
        int jj = idx >> 6, ii = idx & 63;
        float g = sgc[jj];
        float v = tf32f(g * sd[ii][jj] + (1.f - g) * sl[ii][jj]);
        int m = c0 + jj, k = r0 + ii;
        Aout[(size_t)m * 1024 + (k >> 3) * 8 + (k & 3) * 2 + ((k >> 2) & 1)] = v;
    }
}

// ---------------------------------------------------------------------------
// Unified GEMM on packed operands. BM=64, BN=256, BK=32.
// 8 warps (2m x 4n), warp tile 32x64. 2-stage cp.async, 2 CTAs/SM.
// All fragment loads are single LDS.64, conflict-free.
// smem stage: A 64 rows x 40 words (10240 B) + X 16 rows x 260 float2 (33280 B)
// ---------------------------------------------------------------------------
#define G_STAGE 43520
#define G_SMEM (2 * G_STAGE)

__global__ __launch_bounds__(256, 2) void ax_gemm(int dummy) {
    extern __shared__ char smem[];
    const uint32_t sb = smem_u32(smem);
    const int tid = threadIdx.x, lane = tid & 31, wid = tid >> 5;
    const int id = blockIdx.x;
    const int side = id & 1;
    const int m0 = (id >> 1) * 64;
    const int b = blockIdx.y;
    const int cc = lane & 3, gg = lane >> 2;

    const char* Ab = (const char*)((side ? g_Aoutp : g_Ainp) +
                                   (size_t)b * (NN * NN / 2) + (size_t)m0 * 512);
    const char* Xb = (const char*)(g_xp + (size_t)b * 128 * 4 * DD);
    float* outb = (side ? g_axout : g_axin) + (size_t)b * NN * DD + (size_t)m0 * DD;

    auto issue = [&](int it) {
        const uint32_t so = sb + (it & 1) * G_STAGE;
        // A: 64 rows x 128 B contiguous (K8 = it*4 .. it*4+3)
#pragma unroll
        for (int i = 0; i < 2; i++) {
            int idx = tid + i * 256;
            int r = idx >> 3, ch = idx & 7;
            CP16(so + r * 160 + ch * 16, Ab + (size_t)r * 4096 + it * 128 + ch * 16);
        }
        // X: 16 rows ((K8,c)) x 2048 B each
#pragma unroll
        for (int i = 0; i < 8; i++) {
            int idx = tid + i * 256;
            int row = idx >> 7, ch = idx & 127;
            CP16(so + 10240 + row * 2080 + ch * 16,
                 Xb + (size_t)(it * 16 + row) * 2048 + ch * 16);
        }
        CPCOMMIT();
    };

    issue(0);

    float acc[2][8][4] = {};
    const int wm = wid & 1, wn = wid >> 1;

    for (int it = 0; it < 32; it++) {
        if (it + 1 < 32) issue(it + 1); else CPCOMMIT();
        CPWAIT1();
        __syncthreads();
        const char* st = smem + (it & 1) * G_STAGE;
        const float2* sA = (const float2*)st;          // row stride 20 float2
        const float2* sX = (const float2*)(st + 10240);  // row stride 260 float2
#pragma unroll
        for (int k8 = 0; k8 < 4; k8++) {
            uint32_t a[2][4], bx[8][2];
#pragma unroll
            for (int mt = 0; mt < 2; mt++) {
                int r = wm * 32 + mt * 16 + gg;
                float2 u = sA[r * 20 + k8 * 4 + cc];
                float2 v = sA[(r + 8) * 20 + k8 * 4 + cc];
                a[mt][0] = __float_as_uint(u.x);
                a[mt][1] = __float_as_uint(v.x);
                a[mt][2] = __float_as_uint(u.y);
                a[mt][3] = __float_as_uint(v.y);
            }
#pragma unroll
            for (int nt = 0; nt < 8; nt++) {
                int n = wn * 64 + nt * 8 + gg;
                float2 w = sX[(k8 * 4 + cc) * 260 + n];
                bx[nt][0] = __float_as_uint(w.x);
                bx[nt][1] = __float_as_uint(w.y);
            }
#pragma unroll
            for (int mt = 0; mt < 2; mt++)
#pragma unroll
                for (int nt = 0; nt < 8; nt++) mma8(acc[mt][nt], a[mt], bx[nt]);
        }
        __syncthreads();
    }

#pragma unroll
    for (int mt = 0; mt < 2; mt++) {
        int r0 = wm * 32 + mt * 16 + gg;
        float* o0 = outb + (size_t)r0 * DD;
        float* o1 = o0 + 8 * DD;
#pragma unroll
        for (int nt = 0; nt < 8; nt++) {
            int c = wn * 64 + nt * 8 + cc * 2;
            *(float2*)(o0 + c) = make_float2(acc[mt][nt][0], acc[mt][nt][1]);
            *(float2*)(o1 + c) = make_float2(acc[mt][nt][2], acc[mt][nt][3]);
        }
    }
}

// ---------------------------------------------------------------------------
// hfuse: gcn gates + residual (fp32 x), then dual fc (tf32), LN, exact GELU
// ---------------------------------------------------------------------------
#define HF_SUF 67584                 // 2*32*264*4
#define HF_SMEM (HF_SUF + 40960)     // + 2*128*40*4

__global__ __launch_bounds__(256) void hfuse_kernel(
    const float* __restrict__ x,
    const float* __restrict__ Wi, const float* __restrict__ Wo,
    const float* __restrict__ bi, const float* __restrict__ bo,
    const float* __restrict__ wgi, const float* __restrict__ wgo,
    const float* __restrict__ bgi, const float* __restrict__ bgo,
    const float* __restrict__ lng, const float* __restrict__ lnb,
    float* __restrict__ out) {
    extern __shared__ char smem[];
    float* sUf = (float*)smem;            // [side][32][264]
    float* sW = (float*)(smem + HF_SUF);  // [side][128][40]

    const int row0 = blockIdx.x * 32;
    const int tid = threadIdx.x;
    const int lane = tid & 31;
    const int wid = tid >> 5;
    const int cc = lane & 3, gg = lane >> 2;

    const float bgi0 = bgi[0], bgo0 = bgo[0];
#pragma unroll
    for (int i = 0; i < 4; i++) {
        int r = wid * 4 + i;
        size_t base = (size_t)(row0 + r) * DD;
        float ui[8], uo[8], xv[8];
        float si = 0.f, so = 0.f;
#pragma unroll
        for (int jj = 0; jj < 8; jj++) {
            int d = lane + jj * 32;
            ui[jj] = g_axin[base + d];
            uo[jj] = g_axout[base + d];
            xv[jj] = x[base + d];
            si += ui[jj] * wgi[d];
            so += uo[jj] * wgo[d];
        }
#pragma unroll
        for (int o = 16; o; o >>= 1) {
            si += __shfl_xor_sync(0xffffffffu, si, o);
            so += __shfl_xor_sync(0xffffffffu, so, o);
        }
        si = 1.f / (1.f + expf(-si));
        so = 1.f / (1.f + expf(-so));
#pragma unroll
        for (int jj = 0; jj < 8; jj++) {
            int d = lane + jj * 32;
            sUf[r * 264 + d] = tf32f(ui[jj] * si + bgi0 + xv[jj]);
            sUf[32 * 264 + r * 264 + d] = tf32f(uo[jj] * so + bgo0 + xv[jj]);
        }
    }
    __syncthreads();

    const int side = wid >> 2;
    const int nb = (wid & 3) * 32;
    const float* su = sUf + side * 32 * 264;
    float* swb = sW + side * 128 * 40;

    float acc[2][4][4] = {};
    for (int k0 = 0; k0 < DD; k0 += 32) {
#pragma unroll
        for (int s = 0; s < 2; s++) {
            const float* Wsrc = s ? Wo : Wi;
            float* wdst = sW + s * 128 * 40;
#pragma unroll
            for (int i2 = 0; i2 < 4; i2++) {
                int idx = tid + i2 * 256;
                int h = idx >> 3, c4 = idx & 7;
                float4 v = *(const float4*)(Wsrc + (size_t)h * DD + k0 + c4 * 4);
                float4 w = make_float4(tf32f(v.x), tf32f(v.y), tf32f(v.z), tf32f(v.w));
                *(float4*)(wdst + h * 40 + c4 * 4) = w;
            }
        }
        __syncthreads();

#pragma unroll
        for (int j = 0; j < 4; j++) {
            const int kp = j * 8 + 2 * cc;
            uint32_t a[2][4], bb[4][2];
#pragma unroll
            for (int mt = 0; mt < 2; mt++) {
                int r = mt * 16 + gg;
                float2 v0 = *(const float2*)(su + r * 264 + k0 + kp);
                float2 v1 = *(const float2*)(su + (r + 8) * 264 + k0 + kp);
                a[mt][0] = __float_as_uint(v0.x);
                a[mt][1] = __float_as_uint(v1.x);
                a[mt][2] = __float_as_uint(v0.y);
                a[mt][3] = __float_as_uint(v1.y);
            }
#pragma unroll
            for (int nt = 0; nt < 4; nt++) {
                int n = nb + nt * 8 + gg;
                float2 v = *(const float2*)(swb + n * 40 + kp);
                bb[nt][0] = __float_as_uint(v.x);
                bb[nt][1] = __float_as_uint(v.y);
            }
#pragma unroll
            for (int mt = 0; mt < 2; mt++)
#pragma unroll
                for (int nt = 0; nt < 4; nt++) mma8(acc[mt][nt], a[mt], bb[nt]);
        }
        __syncthreads();
    }

    float* sHp = sW;  // [32][264]
    const float* bias = side ? bo : bi;
#pragma unroll
    for (int mt = 0; mt < 2; mt++) {
#pragma unroll
        for (int nt = 0; nt < 4; nt++) {
            int cl = nb + nt * 8 + cc * 2;
            float b0 = 2.f * bias[cl], b1 = 2.f * bias[cl + 1];
            int col = side * HH + cl;
            int r = mt * 16 + gg;
            sHp[r * 264 + col] = acc[mt][nt][0] + b0;
            sHp[r * 264 + col + 1] = acc[mt][nt][1] + b1;
            sHp[(r + 8) * 264 + col] = acc[mt][nt][2] + b0;
            sHp[(r + 8) * 264 + col + 1] = acc[mt][nt][3] + b1;
        }
    }
    __syncthreads();

#pragma unroll
    for (int i = 0; i < 4; i++) {
        int r = wid * 4 + i;
        float v[8];
        float s = 0.f, sq = 0.f;
#pragma unroll
        for (int jj = 0; jj < 8; jj++) {
            v[jj] = sHp[r * 264 + lane + jj * 32];
            s += v[jj];
            sq += v[jj] * v[jj];
        }
#pragma unroll
        for (int o = 16; o; o >>= 1) {
            s += __shfl_xor_sync(0xffffffffu, s, o);
            sq += __shfl_xor_sync(0xffffffffu, sq, o);
        }
        float mu = s * (1.f / 256.f);
        float var = sq * (1.f / 256.f) - mu * mu;
        float rs = rsqrtf(var + 1e-5f);
#pragma unroll
        for (int jj = 0; jj < 8; jj++) {
            int col = lane + jj * 32;
            float y = (v[jj] - mu) * rs * lng[col] + lnb[col];
            float ge = 0.5f * y * (1.f + erff(y * 0.70710678118654752f));
            out[(size_t)(row0 + r) * DD + col] = ge;
        }
    }
}

// ---------------------------------------------------------------------------
extern "C" void kernel_launch(void* const* d_in, const int* in_sizes, int n_in,
                              void* d_out, int out_size) {
    (void)in_sizes; (void)n_in; (void)out_size;
    const float* x0  = (const float*)d_in[0];
    const float* lat = (const float*)d_in[1];
    const float* dep = (const float*)d_in[2];
    const float* rg  = (const float*)d_in[3];
    const float* wgi = (const float*)d_in[4];
    const float* bgi = (const float*)d_in[5];
    const float* wgo = (const float*)d_in[6];
    const float* bgo = (const float*)d_in[7];
    const float* fiw = (const float*)d_in[8];
    const float* fib = (const float*)d_in[9];
    const float* fow = (const float*)d_in[10];
    const float* fob = (const float*)d_in[11];
    const float* lng = (const float*)d_in[12];
    const float* lnb = (const float*)d_in[13];
    float* out = (float*)d_out;

    float* xbuf_p = nullptr;
    cudaGetSymbolAddress((void**)&xbuf_p, g_xbuf);

    cudaFuncSetAttribute(ax_gemm, cudaFuncAttributeMaxDynamicSharedMemorySize, G_SMEM);
    cudaFuncSetAttribute(hfuse_kernel, cudaFuncAttributeMaxDynamicSharedMemorySize, HF_SMEM);

    for (int l = 0; l < 2; l++) {
        const float* x = (l == 0) ? x0 : (const float*)xbuf_p;
        float* xo = (l == 1) ? out : xbuf_p;
        gate_kernel<<<2048, dim3(32, 8)>>>(x, rg + l * DD);
        xpack_k<<<dim3(128, 16), 256>>>(x);
        blend_k<<<dim3(16, 16, 16), 256>>>(dep, lat);
        ax_gemm<<<dim3(32, 16), 256, G_SMEM>>>(0);
        hfuse_kernel<<<512, 256, HF_SMEM>>>(
            x,
            fiw + (size_t)l * HH * DD, fow + (size_t)l * HH * DD,
            fib + l * HH, fob + l * HH,
            wgi + l * DD, wgo + l * DD, bgi + l, bgo + l,
            lng + l * 2 * HH, lnb + l * 2 * HH, xo);
    }
}